// round 5
// baseline (speedup 1.0000x reference)
#include <cuda_runtime.h>

#define NIMG 1024          // B*R = 16*64
#define KC_THREADS 384

// ---- scratch (static device arrays: no allocation allowed) ----
__device__ float g_pooled1[NIMG * 64 * 30 * 30];   // conv1+pool1 output, [img][c][30][30]
__device__ int   g_bounds[NIMG][2][4];             // per pair, per channel: jx1 jx2 iy1 iy2
__device__ float g_w2t[64 * 25 * 32];              // conv2 weights transposed: [c][dy][dx][oc]

// ---------------- packed f32x2 helpers ----------------
__device__ __forceinline__ unsigned long long fma2(unsigned long long a,
                                                   unsigned long long b,
                                                   unsigned long long c) {
    unsigned long long d;
    asm("fma.rn.f32x2 %0, %1, %2, %3;" : "=l"(d) : "l"(a), "l"(b), "l"(c));
    return d;
}
__device__ __forceinline__ unsigned long long dup2(float v) {
    unsigned long long d;
    asm("mov.b64 %0, {%1, %1};" : "=l"(d) : "f"(v));
    return d;
}
__device__ __forceinline__ float2 u2f(unsigned long long u) {
    float2 f;
    asm("mov.b64 {%0, %1}, %2;" : "=f"(f.x), "=f"(f.y) : "l"(u));
    return f;
}
__device__ __forceinline__ void load_row(unsigned long long* d, const float* p) {
    float4 a = *(const float4*)p;
    float4 b = *(const float4*)(p + 4);
    d[0] = dup2(a.x); d[1] = dup2(a.y); d[2] = dup2(a.z); d[3] = dup2(a.w);
    d[4] = dup2(b.x); d[5] = dup2(b.y); d[6] = dup2(b.z); d[7] = dup2(b.w);
}

// ---------------- Kernel A: integer rect bounds per (pair, channel) ----------------
__global__ void k_bounds(const float* __restrict__ bboxes,
                         const int*   __restrict__ pairs) {
    int n = blockIdx.x * blockDim.x + threadIdx.x;
    if (n >= NIMG) return;
    int b  = n >> 6;                 // R = 64
    int p0 = pairs[n * 2 + 0];
    int p1 = pairs[n * 2 + 1];
    const float* B0 = bboxes + (b * 32 + p0) * 4;
    const float* B1 = bboxes + (b * 32 + p1) * 4;
    float bx1[2] = {B0[0], B1[0]}, by1[2] = {B0[1], B1[1]};
    float bx2[2] = {B0[2], B1[2]}, by2[2] = {B0[3], B1[3]};
    float ux1 = fminf(bx1[0], bx1[1]), uy1 = fminf(by1[0], by1[1]);
    float ux2 = fmaxf(bx2[0], bx2[1]), uy2 = fmaxf(by2[0], by2[1]);
    float uw = fmaxf(ux2 - ux1, 1e-6f), uh = fmaxf(uy2 - uy1, 1e-6f);
    for (int c = 0; c < 2; ++c) {
        float x1 = (bx1[c] - ux1) / uw * 64.0f;
        float y1 = (by1[c] - uy1) / uh * 64.0f;
        float x2 = (bx2[c] - ux1) / uw * 64.0f;
        float y2 = (by2[c] - uy1) / uh * 64.0f;
        int jlo = 64, jhi = -1, ilo = 64, ihi = -1;
        for (int k = 0; k < 64; ++k) {
            float f = (float)k + 0.5f;
            if (f >= x1 && f <= x2) { if (k < jlo) jlo = k; jhi = k; }
            if (f >= y1 && f <= y2) { if (k < ilo) ilo = k; ihi = k; }
        }
        g_bounds[n][c][0] = jlo; g_bounds[n][c][1] = jhi;
        g_bounds[n][c][2] = ilo; g_bounds[n][c][3] = ihi;
    }
}

// ---------------- Kernel A2: transpose conv2 weights to [c][dy][dx][oc] ----------------
__global__ void k_wtrans(const float* __restrict__ w2) {
    int i = blockIdx.x * blockDim.x + threadIdx.x;
    if (i >= 64 * 25 * 32) return;
    int oc = i & 31;
    int rest = i >> 5;
    int dx = rest % 5;
    int r2 = rest / 5;
    int dy = r2 % 5;
    int c  = r2 / 5;
    g_w2t[i] = w2[((oc * 64 + c) * 5 + dy) * 5 + dx];
}

// ---------------- Kernel B: conv1 + bias + maxpool2 via 2D weight prefix sums ----------------
__global__ void __launch_bounds__(512, 1)
k_conv1pool(const float* __restrict__ w1,
            const float* __restrict__ b1) {
    __shared__ float P[64 * 2 * 36];     // [o][c][6][6] prefix
    __shared__ float bias[64];
    __shared__ int wy[2][60], wx[2][60]; // packed window codes: lo | (hiEx<<4)
    int img = blockIdx.x, t = threadIdx.x;

    if (t < 128) {
        int o = t >> 1, c = t & 1;
        float wloc[25];
#pragma unroll
        for (int k = 0; k < 25; ++k) wloc[k] = w1[(o * 2 + c) * 25 + k];
        float* Pt = &P[(o * 2 + c) * 36];
#pragma unroll
        for (int bb = 0; bb < 6; ++bb) Pt[bb] = 0.0f;
#pragma unroll
        for (int a = 1; a < 6; ++a) {
            Pt[a * 6] = 0.0f;
            float rs = 0.0f;
#pragma unroll
            for (int bb = 1; bb < 6; ++bb) {
                rs += wloc[(a - 1) * 5 + (bb - 1)];
                Pt[a * 6 + bb] = Pt[(a - 1) * 6 + bb] + rs;
            }
        }
    }
    if (t < 64) bias[t] = b1[t];
    if (t < 240) {
        int c = t & 1;
        int rest = t >> 1;
        int pos = rest % 60;
        int dim = rest / 60;
        int lo = g_bounds[img][c][dim ? 2 : 0];
        int hi = g_bounds[img][c][dim ? 3 : 1];
        int l = lo - pos;      l = max(0, min(5, l));
        int h = hi + 1 - pos;  h = max(l, min(5, h));
        int code = l | (h << 4);
        if (dim) wy[c][pos] = code; else wx[c][pos] = code;
    }
    __syncthreads();

    float* outp = g_pooled1 + (size_t)img * 57600;
#pragma unroll
    for (int p = 0; p < 2; ++p) {
        int pix = t + p * 512;
        if (pix >= 900) break;
        int I = pix / 30, J = pix - I * 30;
        int yl6[2][2], yh6[2][2], xl[2][2], xh[2][2];
#pragma unroll
        for (int c = 0; c < 2; ++c) {
#pragma unroll
            for (int s = 0; s < 2; ++s) {
                int cy = wy[c][2 * I + s];
                yl6[c][s] = (cy & 15) * 6; yh6[c][s] = (cy >> 4) * 6;
                int cx = wx[c][2 * J + s];
                xl[c][s] = cx & 15; xh[c][s] = cx >> 4;
            }
        }
        const float* Pb = P;
        for (int o = 0; o < 64; ++o, Pb += 72) {
            float m = -1e30f;
#pragma unroll
            for (int iy = 0; iy < 2; ++iy) {
#pragma unroll
                for (int jx = 0; jx < 2; ++jx) {
                    float v = bias[o];
#pragma unroll
                    for (int c = 0; c < 2; ++c) {
                        const float* Pc = Pb + c * 36;
                        v += Pc[yh6[c][iy] + xh[c][jx]] - Pc[yl6[c][iy] + xh[c][jx]]
                           - Pc[yh6[c][iy] + xl[c][jx]] + Pc[yl6[c][iy] + xl[c][jx]];
                    }
                    m = fmaxf(m, v);
                }
            }
            outp[o * 900 + pix] = m;
        }
    }
}

// ---------------- Kernel C: conv2 + bias + maxpool2 + mean + fc + relu (fused) ----------------
// One CTA per image, 384 threads. Each active thread: 2 out-rows (one pool pair) x
// 4 out-cols x 8 oc. Weight LDS shared across both rows (halves weight wavefronts);
// input rows double-buffered in registers across dy (1 new row per dy).
__global__ void __launch_bounds__(KC_THREADS, 1)
k_conv2tail(const float* __restrict__ b2,
            const float* __restrict__ fcw,
            const float* __restrict__ fcb,
            float* __restrict__ out) {
    extern __shared__ float sh[];
    float* ins = sh;             // 16 * 30 * 32 = 15360 floats (x-stride 32, cols 30,31 zero)
    float* ws  = sh + 15360;     // 16 * 25 * 32 = 12800 floats, [cc][dy][dx][oc]
    __shared__ float sfeat[32];
    __shared__ float sb2[32];

    int img = blockIdx.x, t = threadIdx.x;
    if (t < 32) sb2[t] = b2[t];
    int ocg = t & 3;                   // 0..3 (8 oc each)
    int r   = t >> 2;                  // 0..95
    bool act = r < 91;                 // 13 rowpairs * 7 colgroups
    int R    = r / 7;                  // 0..12  (out rows 2R, 2R+1)
    int colg = r - R * 7;              // 0..6
    int j0   = colg * 4;               // output col base (0..24)
    int y0   = 2 * R;

    unsigned long long acc[32];        // [row 0..1][col 0..3][q 0..3]
#pragma unroll
    for (int q = 0; q < 32; ++q) acc[q] = 0ull;

    for (int cg = 0; cg < 4; ++cg) {
        __syncthreads();   // previous chunk's compute done before overwrite
        // fill 16-channel input chunk: rows padded to 32 floats, cols 30,31 zeroed
        const float2* src = (const float2*)(g_pooled1 + (size_t)img * 57600 + cg * 14400);
        for (int i2 = t; i2 < 7680; i2 += KC_THREADS) {
            int x2 = i2 & 15;
            int rest = i2 >> 4;
            int y  = rest % 30;
            int cc = rest / 30;
            float2 v = (x2 < 15) ? src[cc * 450 + y * 15 + x2] : make_float2(0.f, 0.f);
            *(float2*)(ins + cc * 960 + y * 32 + x2 * 2) = v;
        }
        // load weight chunk (contiguous, float4)
        const float4* wsrc = (const float4*)(g_w2t + cg * 12800);
        float4* wdst = (float4*)ws;
        for (int i4 = t; i4 < 3200; i4 += KC_THREADS) wdst[i4] = wsrc[i4];
        __syncthreads();

        if (act) {
#pragma unroll 1
            for (int cc = 0; cc < 16; ++cc) {
                const float* inc = ins + cc * 960 + y0 * 32 + j0;
                const float* wcc = ws + cc * 800 + ocg * 8;
                unsigned long long buf0[8], buf1[8];
                load_row(buf0, inc);            // row y0
                load_row(buf1, inc + 32);       // row y0+1
#pragma unroll
                for (int dy = 0; dy < 5; ++dy) {
                    unsigned long long* dA = (dy & 1) ? buf1 : buf0;  // row y0+dy
                    unsigned long long* dB = (dy & 1) ? buf0 : buf1;  // row y0+dy+1
#pragma unroll
                    for (int dx = 0; dx < 5; ++dx) {
                        const ulonglong2* wp =
                            (const ulonglong2*)(wcc + (dy * 5 + dx) * 32);
                        ulonglong2 w0 = wp[0], w1 = wp[1];
                        unsigned long long w[4] = {w0.x, w0.y, w1.x, w1.y};
#pragma unroll
                        for (int c = 0; c < 4; ++c) {
#pragma unroll
                            for (int q = 0; q < 4; ++q) {
                                acc[c * 4 + q]      = fma2(dA[c + dx], w[q], acc[c * 4 + q]);
                                acc[16 + c * 4 + q] = fma2(dB[c + dx], w[q], acc[16 + c * 4 + q]);
                            }
                        }
                    }
                    if (dy < 4) load_row((dy & 1) ? buf1 : buf0, inc + (dy + 2) * 32);
                }
            }
        }
    }

    // ---- pool2 (2x2 max: rows in-register, col pairs) + mean(13x13) + conv2 bias ----
    __syncthreads();
    float* red = sh;   // reuse: [13 rowpairs][14 col-pairs][32 oc] = 5824 floats
    if (act) {
        int pj0 = colg * 2;
#pragma unroll
        for (int q = 0; q < 4; ++q) {
            // row-max per col, then col-pair max
            float m[4][2];
#pragma unroll
            for (int c = 0; c < 4; ++c) {
                float2 a = u2f(acc[c * 4 + q]);
                float2 b = u2f(acc[16 + c * 4 + q]);
                m[c][0] = fmaxf(a.x, b.x);
                m[c][1] = fmaxf(a.y, b.y);
            }
            int oc = ocg * 8 + q * 2;
            red[(R * 14 + pj0) * 32 + oc]         = fmaxf(m[0][0], m[1][0]);
            red[(R * 14 + pj0) * 32 + oc + 1]     = fmaxf(m[0][1], m[1][1]);
            red[(R * 14 + pj0 + 1) * 32 + oc]     = fmaxf(m[2][0], m[3][0]);
            red[(R * 14 + pj0 + 1) * 32 + oc + 1] = fmaxf(m[2][1], m[3][1]);
        }
    }
    __syncthreads();
    if (t < 32) {
        float s = 0.0f;
        for (int I = 0; I < 13; ++I) {
#pragma unroll
            for (int J = 0; J < 13; ++J)
                s += red[(I * 14 + J) * 32 + t];
        }
        sfeat[t] = s * (1.0f / 169.0f) + sb2[t];
    }
    __syncthreads();

    // ---- fc 32 -> 512 + relu ----
#pragma unroll
    for (int pass = 0; pass < 2; ++pass) {
        int o = t + pass * KC_THREADS;
        if (o < 512) {
            const float4* wv = (const float4*)(fcw + o * 32);
            float s = fcb[o];
#pragma unroll
            for (int q = 0; q < 8; ++q) {
                float4 w = wv[q];
                s += w.x * sfeat[q * 4 + 0] + w.y * sfeat[q * 4 + 1]
                   + w.z * sfeat[q * 4 + 2] + w.w * sfeat[q * 4 + 3];
            }
            out[(size_t)img * 512 + o] = fmaxf(s, 0.0f);
        }
    }
}

// ---------------- launch ----------------
extern "C" void kernel_launch(void* const* d_in, const int* in_sizes, int n_in,
                              void* d_out, int out_size) {
    const float* bboxes = (const float*)d_in[0];
    const int*   pairs  = (const int*)d_in[3];
    const float* w1     = (const float*)d_in[4];
    const float* b1     = (const float*)d_in[5];
    const float* w2     = (const float*)d_in[6];
    const float* b2     = (const float*)d_in[7];
    const float* fcw    = (const float*)d_in[8];
    const float* fcb    = (const float*)d_in[9];
    float* out = (float*)d_out;

    k_bounds<<<4, 256>>>(bboxes, pairs);
    k_wtrans<<<50, 1024>>>(w2);
    k_conv1pool<<<NIMG, 512>>>(w1, b1);

    static const int kSmem = (15360 + 12800) * 4;   // 112,640 B
    cudaFuncSetAttribute(k_conv2tail, cudaFuncAttributeMaxDynamicSharedMemorySize, kSmem);
    k_conv2tail<<<NIMG, KC_THREADS, kSmem>>>(b2, fcw, fcb, out);
}

// round 7
// speedup vs baseline: 1.6952x; 1.6952x over previous
#include <cuda_runtime.h>

#define NIMG 1024          // B*R = 16*64
#define KC_THREADS 768

// ---- scratch (static device arrays: no allocation allowed) ----
__device__ float g_pooled1[NIMG * 64 * 30 * 30];   // conv1+pool1 output, [img][c][30][30]
__device__ int   g_bounds[NIMG][2][4];             // per pair, per channel: jx1 jx2 iy1 iy2
__device__ float g_w2t[64 * 25 * 32];              // conv2 weights transposed: [c][dy][dx][oc]

// ---------------- packed f32x2 helpers ----------------
__device__ __forceinline__ unsigned long long fma2(unsigned long long a,
                                                   unsigned long long b,
                                                   unsigned long long c) {
    unsigned long long d;
    asm("fma.rn.f32x2 %0, %1, %2, %3;" : "=l"(d) : "l"(a), "l"(b), "l"(c));
    return d;
}
__device__ __forceinline__ unsigned long long dup2(float v) {
    unsigned long long d;
    asm("mov.b64 %0, {%1, %1};" : "=l"(d) : "f"(v));
    return d;
}
__device__ __forceinline__ float2 u2f(unsigned long long u) {
    float2 f;
    asm("mov.b64 {%0, %1}, %2;" : "=f"(f.x), "=f"(f.y) : "l"(u));
    return f;
}
__device__ __forceinline__ void load_row(unsigned long long* d, const float* p) {
    float4 a = *(const float4*)p;
    float4 b = *(const float4*)(p + 4);
    d[0] = dup2(a.x); d[1] = dup2(a.y); d[2] = dup2(a.z); d[3] = dup2(a.w);
    d[4] = dup2(b.x); d[5] = dup2(b.y); d[6] = dup2(b.z); d[7] = dup2(b.w);
}

// ---------------- Kernel A: integer rect bounds per (pair, channel) ----------------
__global__ void k_bounds(const float* __restrict__ bboxes,
                         const int*   __restrict__ pairs) {
    int n = blockIdx.x * blockDim.x + threadIdx.x;
    if (n >= NIMG) return;
    int b  = n >> 6;                 // R = 64
    int p0 = pairs[n * 2 + 0];
    int p1 = pairs[n * 2 + 1];
    const float* B0 = bboxes + (b * 32 + p0) * 4;
    const float* B1 = bboxes + (b * 32 + p1) * 4;
    float bx1[2] = {B0[0], B1[0]}, by1[2] = {B0[1], B1[1]};
    float bx2[2] = {B0[2], B1[2]}, by2[2] = {B0[3], B1[3]};
    float ux1 = fminf(bx1[0], bx1[1]), uy1 = fminf(by1[0], by1[1]);
    float ux2 = fmaxf(bx2[0], bx2[1]), uy2 = fmaxf(by2[0], by2[1]);
    float uw = fmaxf(ux2 - ux1, 1e-6f), uh = fmaxf(uy2 - uy1, 1e-6f);
    for (int c = 0; c < 2; ++c) {
        float x1 = (bx1[c] - ux1) / uw * 64.0f;
        float y1 = (by1[c] - uy1) / uh * 64.0f;
        float x2 = (bx2[c] - ux1) / uw * 64.0f;
        float y2 = (by2[c] - uy1) / uh * 64.0f;
        int jlo = 64, jhi = -1, ilo = 64, ihi = -1;
        for (int k = 0; k < 64; ++k) {
            float f = (float)k + 0.5f;
            if (f >= x1 && f <= x2) { if (k < jlo) jlo = k; jhi = k; }
            if (f >= y1 && f <= y2) { if (k < ilo) ilo = k; ihi = k; }
        }
        g_bounds[n][c][0] = jlo; g_bounds[n][c][1] = jhi;
        g_bounds[n][c][2] = ilo; g_bounds[n][c][3] = ihi;
    }
}

// ---------------- Kernel A2: transpose conv2 weights to [c][dy][dx][oc] ----------------
__global__ void k_wtrans(const float* __restrict__ w2) {
    int i = blockIdx.x * blockDim.x + threadIdx.x;
    if (i >= 64 * 25 * 32) return;
    int oc = i & 31;
    int rest = i >> 5;
    int dx = rest % 5;
    int r2 = rest / 5;
    int dy = r2 % 5;
    int c  = r2 / 5;
    g_w2t[i] = w2[((oc * 64 + c) * 5 + dy) * 5 + dx];
}

// ---------------- Kernel B: conv1 + bias + maxpool2 via 2D weight prefix sums ----------------
__global__ void __launch_bounds__(512, 1)
k_conv1pool(const float* __restrict__ w1,
            const float* __restrict__ b1) {
    __shared__ float P[64 * 2 * 36];     // [o][c][6][6] prefix
    __shared__ float bias[64];
    __shared__ int wy[2][60], wx[2][60]; // packed window codes: lo | (hiEx<<4)
    int img = blockIdx.x, t = threadIdx.x;

    if (t < 128) {
        int o = t >> 1, c = t & 1;
        float wloc[25];
#pragma unroll
        for (int k = 0; k < 25; ++k) wloc[k] = w1[(o * 2 + c) * 25 + k];
        float* Pt = &P[(o * 2 + c) * 36];
#pragma unroll
        for (int bb = 0; bb < 6; ++bb) Pt[bb] = 0.0f;
#pragma unroll
        for (int a = 1; a < 6; ++a) {
            Pt[a * 6] = 0.0f;
            float rs = 0.0f;
#pragma unroll
            for (int bb = 1; bb < 6; ++bb) {
                rs += wloc[(a - 1) * 5 + (bb - 1)];
                Pt[a * 6 + bb] = Pt[(a - 1) * 6 + bb] + rs;
            }
        }
    }
    if (t < 64) bias[t] = b1[t];
    if (t < 240) {
        int c = t & 1;
        int rest = t >> 1;
        int pos = rest % 60;
        int dim = rest / 60;
        int lo = g_bounds[img][c][dim ? 2 : 0];
        int hi = g_bounds[img][c][dim ? 3 : 1];
        int l = lo - pos;      l = max(0, min(5, l));
        int h = hi + 1 - pos;  h = max(l, min(5, h));
        int code = l | (h << 4);
        if (dim) wy[c][pos] = code; else wx[c][pos] = code;
    }
    __syncthreads();

    float* outp = g_pooled1 + (size_t)img * 57600;
#pragma unroll
    for (int p = 0; p < 2; ++p) {
        int pix = t + p * 512;
        if (pix >= 900) break;
        int I = pix / 30, J = pix - I * 30;
        int yl6[2][2], yh6[2][2], xl[2][2], xh[2][2];
#pragma unroll
        for (int c = 0; c < 2; ++c) {
#pragma unroll
            for (int s = 0; s < 2; ++s) {
                int cy = wy[c][2 * I + s];
                yl6[c][s] = (cy & 15) * 6; yh6[c][s] = (cy >> 4) * 6;
                int cx = wx[c][2 * J + s];
                xl[c][s] = cx & 15; xh[c][s] = cx >> 4;
            }
        }
        const float* Pb = P;
        for (int o = 0; o < 64; ++o, Pb += 72) {
            float m = -1e30f;
#pragma unroll
            for (int iy = 0; iy < 2; ++iy) {
#pragma unroll
                for (int jx = 0; jx < 2; ++jx) {
                    float v = bias[o];
#pragma unroll
                    for (int c = 0; c < 2; ++c) {
                        const float* Pc = Pb + c * 36;
                        v += Pc[yh6[c][iy] + xh[c][jx]] - Pc[yl6[c][iy] + xh[c][jx]]
                           - Pc[yh6[c][iy] + xl[c][jx]] + Pc[yl6[c][iy] + xl[c][jx]];
                    }
                    m = fmaxf(m, v);
                }
            }
            outp[o * 900 + pix] = m;
        }
    }
}

// ---------------- Kernel C: conv2 + bias + maxpool2 + mean + fc + relu (fused) ----------------
// One CTA per image, 768 threads (24 warps). Each active thread: 2 out-rows (one
// pool pair) x 4 out-cols x 4 oc. Weight LDS shared across both rows; input rows
// register-double-buffered across dy (1 new row per dy).
// t = r*8 + ocg: 8 lanes broadcast input; 8 ocg x 16B weights = one 128B line.
__global__ void __launch_bounds__(KC_THREADS, 1)
k_conv2tail(const float* __restrict__ b2,
            const float* __restrict__ fcw,
            const float* __restrict__ fcb,
            float* __restrict__ out) {
    extern __shared__ float sh[];
    float* ins = sh;             // 16 * 30 * 32 = 15360 floats (x-stride 32, cols 30,31 zero)
    float* ws  = sh + 15360;     // 16 * 25 * 32 = 12800 floats, [cc][dy][dx][oc]
    __shared__ float sfeat[32];
    __shared__ float sb2[32];

    int img = blockIdx.x, t = threadIdx.x;
    if (t < 32) sb2[t] = b2[t];
    int ocg = t & 7;                   // 0..7 (4 oc each)
    int r   = t >> 3;                  // 0..95
    bool act = r < 91;                 // 13 rowpairs * 7 colgroups
    int R    = r / 7;                  // 0..12  (out rows 2R, 2R+1)
    int colg = r - R * 7;              // 0..6
    int j0   = colg * 4;               // output col base (0..24)
    int y0   = 2 * R;

    unsigned long long acc[16];        // [row 0..1][px 0..3][ocpair 0..1]
#pragma unroll
    for (int q = 0; q < 16; ++q) acc[q] = 0ull;

    for (int cg = 0; cg < 4; ++cg) {
        __syncthreads();   // previous chunk's compute done before overwrite
        // fill 16-channel input chunk: rows padded to 32 floats, cols 30,31 zeroed
        const float2* src = (const float2*)(g_pooled1 + (size_t)img * 57600 + cg * 14400);
        for (int i2 = t; i2 < 7680; i2 += KC_THREADS) {
            int x2 = i2 & 15;
            int rest = i2 >> 4;
            int y  = rest % 30;
            int cc = rest / 30;
            float2 v = (x2 < 15) ? src[cc * 450 + y * 15 + x2] : make_float2(0.f, 0.f);
            *(float2*)(ins + cc * 960 + y * 32 + x2 * 2) = v;
        }
        // load weight chunk (contiguous, float4)
        const float4* wsrc = (const float4*)(g_w2t + cg * 12800);
        float4* wdst = (float4*)ws;
        for (int i4 = t; i4 < 3200; i4 += KC_THREADS) wdst[i4] = wsrc[i4];
        __syncthreads();

        if (act) {
#pragma unroll 1
            for (int cc = 0; cc < 16; ++cc) {
                const float* inc = ins + cc * 960 + y0 * 32 + j0;
                const float* wcc = ws + cc * 800 + ocg * 4;
                unsigned long long buf0[8], buf1[8];
                load_row(buf0, inc);            // row y0
                load_row(buf1, inc + 32);       // row y0+1
#pragma unroll
                for (int dy = 0; dy < 5; ++dy) {
                    unsigned long long* dA = (dy & 1) ? buf1 : buf0;  // row y0+dy
                    unsigned long long* dB = (dy & 1) ? buf0 : buf1;  // row y0+dy+1
#pragma unroll
                    for (int dx = 0; dx < 5; ++dx) {
                        ulonglong2 w =
                            *(const ulonglong2*)(wcc + (dy * 5 + dx) * 32);
#pragma unroll
                        for (int c = 0; c < 4; ++c) {
                            acc[c * 2 + 0]     = fma2(dA[c + dx], w.x, acc[c * 2 + 0]);
                            acc[c * 2 + 1]     = fma2(dA[c + dx], w.y, acc[c * 2 + 1]);
                            acc[8 + c * 2 + 0] = fma2(dB[c + dx], w.x, acc[8 + c * 2 + 0]);
                            acc[8 + c * 2 + 1] = fma2(dB[c + dx], w.y, acc[8 + c * 2 + 1]);
                        }
                    }
                    if (dy < 4) load_row((dy & 1) ? buf1 : buf0, inc + (dy + 2) * 32);
                }
            }
        }
    }

    // ---- pool2 (2x2 max: rows in-register, col pairs) + mean(13x13) + conv2 bias ----
    __syncthreads();
    float* red = sh;   // reuse: [13 rowpairs][14 col-pairs][32 oc] = 5824 floats
    if (act) {
        int pj0 = colg * 2;
#pragma unroll
        for (int o = 0; o < 2; ++o) {       // oc pair index
#pragma unroll
            for (int cp = 0; cp < 2; ++cp) { // col-pair index
                float2 a0 = u2f(acc[(2 * cp) * 2 + o]);       // row0, col even
                float2 a1 = u2f(acc[(2 * cp + 1) * 2 + o]);   // row0, col odd
                float2 b0 = u2f(acc[8 + (2 * cp) * 2 + o]);   // row1, col even
                float2 b1 = u2f(acc[8 + (2 * cp + 1) * 2 + o]);
                float mx = fmaxf(fmaxf(a0.x, a1.x), fmaxf(b0.x, b1.x));
                float my = fmaxf(fmaxf(a0.y, a1.y), fmaxf(b0.y, b1.y));
                int oc = ocg * 4 + o * 2;
                red[(R * 14 + pj0 + cp) * 32 + oc]     = mx;
                red[(R * 14 + pj0 + cp) * 32 + oc + 1] = my;
            }
        }
    }
    __syncthreads();
    if (t < 32) {
        float s = 0.0f;
        for (int I = 0; I < 13; ++I) {
#pragma unroll
            for (int J = 0; J < 13; ++J)
                s += red[(I * 14 + J) * 32 + t];
        }
        sfeat[t] = s * (1.0f / 169.0f) + sb2[t];
    }
    __syncthreads();

    // ---- fc 32 -> 512 + relu ----
    if (t < 512) {
        int o = t;
        const float4* wv = (const float4*)(fcw + o * 32);
        float s = fcb[o];
#pragma unroll
        for (int q = 0; q < 8; ++q) {
            float4 w = wv[q];
            s += w.x * sfeat[q * 4 + 0] + w.y * sfeat[q * 4 + 1]
               + w.z * sfeat[q * 4 + 2] + w.w * sfeat[q * 4 + 3];
        }
        out[(size_t)img * 512 + o] = fmaxf(s, 0.0f);
    }
}

// ---------------- launch ----------------
extern "C" void kernel_launch(void* const* d_in, const int* in_sizes, int n_in,
                              void* d_out, int out_size) {
    const float* bboxes = (const float*)d_in[0];
    const int*   pairs  = (const int*)d_in[3];
    const float* w1     = (const float*)d_in[4];
    const float* b1     = (const float*)d_in[5];
    const float* w2     = (const float*)d_in[6];
    const float* b2     = (const float*)d_in[7];
    const float* fcw    = (const float*)d_in[8];
    const float* fcb    = (const float*)d_in[9];
    float* out = (float*)d_out;

    k_bounds<<<4, 256>>>(bboxes, pairs);
    k_wtrans<<<50, 1024>>>(w2);
    k_conv1pool<<<NIMG, 512>>>(w1, b1);

    static const int kSmem = (15360 + 12800) * 4;   // 112,640 B
    cudaFuncSetAttribute(k_conv2tail, cudaFuncAttributeMaxDynamicSharedMemorySize, kSmem);
    k_conv2tail<<<NIMG, KC_THREADS, kSmem>>>(b2, fcw, fcb, out);
}

// round 9
// speedup vs baseline: 1.8003x; 1.0620x over previous
#include <cuda_runtime.h>

#define NIMG 1024          // B*R = 16*64
#define KC_THREADS 768
#define BUFSTRIDE 28160    // floats per buffer: ins 15360 + ws 12800

// ---- scratch (static device arrays: no allocation allowed) ----
__device__ float g_pooled1[NIMG * 64 * 30 * 30];   // conv1+pool1 output, [img][c][30][30]
__device__ int   g_bounds[NIMG][2][4];             // per pair, per channel: jx1 jx2 iy1 iy2
__device__ float g_w2t[64 * 25 * 32];              // conv2 weights transposed: [c][dy][dx][oc]

// ---------------- packed f32x2 helpers ----------------
__device__ __forceinline__ unsigned long long fma2(unsigned long long a,
                                                   unsigned long long b,
                                                   unsigned long long c) {
    unsigned long long d;
    asm("fma.rn.f32x2 %0, %1, %2, %3;" : "=l"(d) : "l"(a), "l"(b), "l"(c));
    return d;
}
__device__ __forceinline__ unsigned long long dup2(float v) {
    unsigned long long d;
    asm("mov.b64 %0, {%1, %1};" : "=l"(d) : "f"(v));
    return d;
}
__device__ __forceinline__ float2 u2f(unsigned long long u) {
    float2 f;
    asm("mov.b64 {%0, %1}, %2;" : "=f"(f.x), "=f"(f.y) : "l"(u));
    return f;
}
__device__ __forceinline__ void load_row(unsigned long long* d, const float* p) {
    float4 a = *(const float4*)p;
    float4 b = *(const float4*)(p + 4);
    d[0] = dup2(a.x); d[1] = dup2(a.y); d[2] = dup2(a.z); d[3] = dup2(a.w);
    d[4] = dup2(b.x); d[5] = dup2(b.y); d[6] = dup2(b.z); d[7] = dup2(b.w);
}

// ---------------- cp.async helpers ----------------
__device__ __forceinline__ void cp_async8(void* dst, const void* src) {
    unsigned d = (unsigned)__cvta_generic_to_shared(dst);
    asm volatile("cp.async.ca.shared.global [%0], [%1], 8;\n" :: "r"(d), "l"(src));
}
__device__ __forceinline__ void cp_async16(void* dst, const void* src) {
    unsigned d = (unsigned)__cvta_generic_to_shared(dst);
    asm volatile("cp.async.cg.shared.global [%0], [%1], 16;\n" :: "r"(d), "l"(src));
}
__device__ __forceinline__ void cp_commit() {
    asm volatile("cp.async.commit_group;\n" ::: "memory");
}
template <int N>
__device__ __forceinline__ void cp_wait() {
    asm volatile("cp.async.wait_group %0;\n" :: "n"(N) : "memory");
}

// ---------------- Kernel A: integer rect bounds per (pair, channel) ----------------
__global__ void k_bounds(const float* __restrict__ bboxes,
                         const int*   __restrict__ pairs) {
    int n = blockIdx.x * blockDim.x + threadIdx.x;
    if (n >= NIMG) return;
    int b  = n >> 6;                 // R = 64
    int p0 = pairs[n * 2 + 0];
    int p1 = pairs[n * 2 + 1];
    const float* B0 = bboxes + (b * 32 + p0) * 4;
    const float* B1 = bboxes + (b * 32 + p1) * 4;
    float bx1[2] = {B0[0], B1[0]}, by1[2] = {B0[1], B1[1]};
    float bx2[2] = {B0[2], B1[2]}, by2[2] = {B0[3], B1[3]};
    float ux1 = fminf(bx1[0], bx1[1]), uy1 = fminf(by1[0], by1[1]);
    float ux2 = fmaxf(bx2[0], bx2[1]), uy2 = fmaxf(by2[0], by2[1]);
    float uw = fmaxf(ux2 - ux1, 1e-6f), uh = fmaxf(uy2 - uy1, 1e-6f);
    for (int c = 0; c < 2; ++c) {
        float x1 = (bx1[c] - ux1) / uw * 64.0f;
        float y1 = (by1[c] - uy1) / uh * 64.0f;
        float x2 = (bx2[c] - ux1) / uw * 64.0f;
        float y2 = (by2[c] - uy1) / uh * 64.0f;
        int jlo = 64, jhi = -1, ilo = 64, ihi = -1;
        for (int k = 0; k < 64; ++k) {
            float f = (float)k + 0.5f;
            if (f >= x1 && f <= x2) { if (k < jlo) jlo = k; jhi = k; }
            if (f >= y1 && f <= y2) { if (k < ilo) ilo = k; ihi = k; }
        }
        g_bounds[n][c][0] = jlo; g_bounds[n][c][1] = jhi;
        g_bounds[n][c][2] = ilo; g_bounds[n][c][3] = ihi;
    }
}

// ---------------- Kernel A2: transpose conv2 weights to [c][dy][dx][oc] ----------------
__global__ void k_wtrans(const float* __restrict__ w2) {
    int i = blockIdx.x * blockDim.x + threadIdx.x;
    if (i >= 64 * 25 * 32) return;
    int oc = i & 31;
    int rest = i >> 5;
    int dx = rest % 5;
    int r2 = rest / 5;
    int dy = r2 % 5;
    int c  = r2 / 5;
    g_w2t[i] = w2[((oc * 64 + c) * 5 + dy) * 5 + dx];
}

// ---------------- Kernel B: conv1 + bias + maxpool2 via 2D weight prefix sums ----------------
__global__ void __launch_bounds__(512, 1)
k_conv1pool(const float* __restrict__ w1,
            const float* __restrict__ b1) {
    __shared__ float P[64 * 2 * 36];     // [o][c][6][6] prefix
    __shared__ float bias[64];
    __shared__ int wy[2][60], wx[2][60]; // packed window codes: lo | (hiEx<<4)
    int img = blockIdx.x, t = threadIdx.x;

    if (t < 128) {
        int o = t >> 1, c = t & 1;
        float wloc[25];
#pragma unroll
        for (int k = 0; k < 25; ++k) wloc[k] = w1[(o * 2 + c) * 25 + k];
        float* Pt = &P[(o * 2 + c) * 36];
#pragma unroll
        for (int bb = 0; bb < 6; ++bb) Pt[bb] = 0.0f;
#pragma unroll
        for (int a = 1; a < 6; ++a) {
            Pt[a * 6] = 0.0f;
            float rs = 0.0f;
#pragma unroll
            for (int bb = 1; bb < 6; ++bb) {
                rs += wloc[(a - 1) * 5 + (bb - 1)];
                Pt[a * 6 + bb] = Pt[(a - 1) * 6 + bb] + rs;
            }
        }
    }
    if (t < 64) bias[t] = b1[t];
    if (t < 240) {
        int c = t & 1;
        int rest = t >> 1;
        int pos = rest % 60;
        int dim = rest / 60;
        int lo = g_bounds[img][c][dim ? 2 : 0];
        int hi = g_bounds[img][c][dim ? 3 : 1];
        int l = lo - pos;      l = max(0, min(5, l));
        int h = hi + 1 - pos;  h = max(l, min(5, h));
        int code = l | (h << 4);
        if (dim) wy[c][pos] = code; else wx[c][pos] = code;
    }
    __syncthreads();

    float* outp = g_pooled1 + (size_t)img * 57600;
#pragma unroll
    for (int p = 0; p < 2; ++p) {
        int pix = t + p * 512;
        if (pix >= 900) break;
        int I = pix / 30, J = pix - I * 30;
        int yl6[2][2], yh6[2][2], xl[2][2], xh[2][2];
#pragma unroll
        for (int c = 0; c < 2; ++c) {
#pragma unroll
            for (int s = 0; s < 2; ++s) {
                int cy = wy[c][2 * I + s];
                yl6[c][s] = (cy & 15) * 6; yh6[c][s] = (cy >> 4) * 6;
                int cx = wx[c][2 * J + s];
                xl[c][s] = cx & 15; xh[c][s] = cx >> 4;
            }
        }
        const float* Pb = P;
        for (int o = 0; o < 64; ++o, Pb += 72) {
            float m = -1e30f;
#pragma unroll
            for (int iy = 0; iy < 2; ++iy) {
#pragma unroll
                for (int jx = 0; jx < 2; ++jx) {
                    float v = bias[o];
#pragma unroll
                    for (int c = 0; c < 2; ++c) {
                        const float* Pc = Pb + c * 36;
                        v += Pc[yh6[c][iy] + xh[c][jx]] - Pc[yl6[c][iy] + xh[c][jx]]
                           - Pc[yh6[c][iy] + xl[c][jx]] + Pc[yl6[c][iy] + xl[c][jx]];
                    }
                    m = fmaxf(m, v);
                }
            }
            outp[o * 900 + pix] = m;
        }
    }
}

// ---------------- Kernel C: conv2 + bias + maxpool2 + mean + fc + relu (fused) ----------------
// One CTA per image, 768 threads (24 warps). Each active thread: 2 out-rows (one
// pool pair) x 4 out-cols x 4 oc. cp.async DOUBLE BUFFERING: chunk cg+2 prefetched
// while chunk cg computes, hiding the DRAM load phases behind FFMA2.
__global__ void __launch_bounds__(KC_THREADS, 1)
k_conv2tail(const float* __restrict__ b2,
            const float* __restrict__ fcw,
            const float* __restrict__ fcb,
            float* __restrict__ out) {
    extern __shared__ float sh[];
    // buffer p (p=0,1): ins at sh + p*BUFSTRIDE (16ch x 30 x 32), ws at +15360
    __shared__ float sfeat[32];
    __shared__ float sb2[32];

    int img = blockIdx.x, t = threadIdx.x;
    if (t < 32) sb2[t] = b2[t];
    int ocg = t & 7;                   // 0..7 (4 oc each)
    int r   = t >> 3;                  // 0..95
    bool act = r < 91;                 // 13 rowpairs * 7 colgroups
    int R    = r / 7;                  // 0..12  (out rows 2R, 2R+1)
    int colg = r - R * 7;              // 0..6
    int j0   = colg * 4;               // output col base (0..24)
    int y0   = 2 * R;

    // zero pad columns 30,31 of every input row, both buffers (cp.async never writes them)
    for (int i = t; i < 960; i += KC_THREADS) {
        int buf = i >= 480;
        int rest = buf ? i - 480 : i;
        int cc = rest / 30, y = rest - cc * 30;
        float* b = sh + buf * BUFSTRIDE + cc * 960 + y * 32;
        b[30] = 0.0f; b[31] = 0.0f;
    }

    const float* gin = g_pooled1 + (size_t)img * 57600;

    // prefetch chunks 0 and 1
#pragma unroll
    for (int pc = 0; pc < 2; ++pc) {
        float* insb = sh + pc * BUFSTRIDE;
        float* wsb  = insb + 15360;
        const float2* src = (const float2*)(gin + pc * 14400);
        for (int i2 = t; i2 < 7200; i2 += KC_THREADS) {
            int x2 = i2 % 15;
            int rest = i2 / 15;
            int y = rest % 30, cc = rest / 30;
            cp_async8(insb + cc * 960 + y * 32 + x2 * 2, src + i2);
        }
        const float4* wsrc = (const float4*)(g_w2t + pc * 12800);
        for (int i4 = t; i4 < 3200; i4 += KC_THREADS)
            cp_async16((float4*)wsb + i4, wsrc + i4);
        cp_commit();
    }

    unsigned long long acc[16];        // [row 0..1][px 0..3][ocpair 0..1]
#pragma unroll
    for (int q = 0; q < 16; ++q) acc[q] = 0ull;

#pragma unroll 1
    for (int cg = 0; cg < 4; ++cg) {
        if (cg < 3) cp_wait<1>(); else cp_wait<0>();
        __syncthreads();   // chunk cg visible to all; previous compute on this buffer done

        float* ins = sh + (cg & 1) * BUFSTRIDE;
        float* ws  = ins + 15360;

        if (act) {
#pragma unroll 1
            for (int cc = 0; cc < 16; ++cc) {
                const float* inc = ins + cc * 960 + y0 * 32 + j0;
                const float* wcc = ws + cc * 800 + ocg * 4;
                unsigned long long buf0[8], buf1[8];
                load_row(buf0, inc);            // row y0
                load_row(buf1, inc + 32);       // row y0+1
#pragma unroll
                for (int dy = 0; dy < 5; ++dy) {
                    unsigned long long* dA = (dy & 1) ? buf1 : buf0;  // row y0+dy
                    unsigned long long* dB = (dy & 1) ? buf0 : buf1;  // row y0+dy+1
#pragma unroll
                    for (int dx = 0; dx < 5; ++dx) {
                        ulonglong2 w =
                            *(const ulonglong2*)(wcc + (dy * 5 + dx) * 32);
#pragma unroll
                        for (int c = 0; c < 4; ++c) {
                            acc[c * 2 + 0]     = fma2(dA[c + dx], w.x, acc[c * 2 + 0]);
                            acc[c * 2 + 1]     = fma2(dA[c + dx], w.y, acc[c * 2 + 1]);
                            acc[8 + c * 2 + 0] = fma2(dB[c + dx], w.x, acc[8 + c * 2 + 0]);
                            acc[8 + c * 2 + 1] = fma2(dB[c + dx], w.y, acc[8 + c * 2 + 1]);
                        }
                    }
                    if (dy < 4) load_row((dy & 1) ? buf1 : buf0, inc + (dy + 2) * 32);
                }
            }
        }
        __syncthreads();   // compute on this buffer finished block-wide

        if (cg < 2) {      // prefetch chunk cg+2 into the buffer just freed
            int nc = cg + 2;
            float* insb = sh + (cg & 1) * BUFSTRIDE;
            float* wsb  = insb + 15360;
            const float2* src = (const float2*)(gin + nc * 14400);
            for (int i2 = t; i2 < 7200; i2 += KC_THREADS) {
                int x2 = i2 % 15;
                int rest = i2 / 15;
                int y = rest % 30, cc = rest / 30;
                cp_async8(insb + cc * 960 + y * 32 + x2 * 2, src + i2);
            }
            const float4* wsrc = (const float4*)(g_w2t + nc * 12800);
            for (int i4 = t; i4 < 3200; i4 += KC_THREADS)
                cp_async16((float4*)wsb + i4, wsrc + i4);
            cp_commit();
        }
    }

    // ---- pool2 (2x2 max: rows in-register, col pairs) + mean(13x13) + conv2 bias ----
    float* red = sh;   // reuse buffer 0: [13 rowpairs][14 col-pairs][32 oc] = 5824 floats
    if (act) {
        int pj0 = colg * 2;
#pragma unroll
        for (int o = 0; o < 2; ++o) {       // oc pair index
#pragma unroll
            for (int cp = 0; cp < 2; ++cp) { // col-pair index
                float2 a0 = u2f(acc[(2 * cp) * 2 + o]);       // row0, col even
                float2 a1 = u2f(acc[(2 * cp + 1) * 2 + o]);   // row0, col odd
                float2 b0 = u2f(acc[8 + (2 * cp) * 2 + o]);   // row1, col even
                float2 b1 = u2f(acc[8 + (2 * cp + 1) * 2 + o]);
                float mx = fmaxf(fmaxf(a0.x, a1.x), fmaxf(b0.x, b1.x));
                float my = fmaxf(fmaxf(a0.y, a1.y), fmaxf(b0.y, b1.y));
                int oc = ocg * 4 + o * 2;
                red[(R * 14 + pj0 + cp) * 32 + oc]     = mx;
                red[(R * 14 + pj0 + cp) * 32 + oc + 1] = my;
            }
        }
    }
    __syncthreads();
    if (t < 32) {
        float s = 0.0f;
        for (int I = 0; I < 13; ++I) {
#pragma unroll
            for (int J = 0; J < 13; ++J)
                s += red[(I * 14 + J) * 32 + t];
        }
        sfeat[t] = s * (1.0f / 169.0f) + sb2[t];
    }
    __syncthreads();

    // ---- fc 32 -> 512 + relu ----
    if (t < 512) {
        int o = t;
        const float4* wv = (const float4*)(fcw + o * 32);
        float s = fcb[o];
#pragma unroll
        for (int q = 0; q < 8; ++q) {
            float4 w = wv[q];
            s += w.x * sfeat[q * 4 + 0] + w.y * sfeat[q * 4 + 1]
               + w.z * sfeat[q * 4 + 2] + w.w * sfeat[q * 4 + 3];
        }
        out[(size_t)img * 512 + o] = fmaxf(s, 0.0f);
    }
}

// ---------------- launch ----------------
extern "C" void kernel_launch(void* const* d_in, const int* in_sizes, int n_in,
                              void* d_out, int out_size) {
    const float* bboxes = (const float*)d_in[0];
    const int*   pairs  = (const int*)d_in[3];
    const float* w1     = (const float*)d_in[4];
    const float* b1     = (const float*)d_in[5];
    const float* w2     = (const float*)d_in[6];
    const float* b2     = (const float*)d_in[7];
    const float* fcw    = (const float*)d_in[8];
    const float* fcb    = (const float*)d_in[9];
    float* out = (float*)d_out;

    k_bounds<<<4, 256>>>(bboxes, pairs);
    k_wtrans<<<50, 1024>>>(w2);
    k_conv1pool<<<NIMG, 512>>>(w1, b1);

    static const int kSmem = 2 * BUFSTRIDE * 4;   // 225,280 B
    cudaFuncSetAttribute(k_conv2tail, cudaFuncAttributeMaxDynamicSharedMemorySize, kSmem);
    k_conv2tail<<<NIMG, KC_THREADS, kSmem>>>(b2, fcw, fcb, out);
}